// round 5
// baseline (speedup 1.0000x reference)
#include <cuda_runtime.h>
#include <cstdint>

// LinearBlendSkinning: out[n] = (sum_j w[n,j]*SE3[j])[:3,:3] @ p[n] + (...)[:3,3]
// N = 1e6 verts, J = 55 joints.
//
// R5 changes vs R4 (68.1us, occ 21.8%, DRAM 45%):
//  - SE3 moved to __constant__ (D2D cudaMemcpyToSymbolAsync, graph-capturable).
//    Warp-uniform SE3 rows now come through the constant/uniform path (LDCU)
//    instead of 3x LDS.128 per joint -> SMEM holds only the weights tile.
//  - BT=128, VPT=1, BV=128 -> smem 28.2KB/block -> 8 blocks/SM, 32 warps/SM
//    (50% occ vs 21.8%). More resident warps = more staging MLP = higher HBM
//    utilization; 8 desynced blocks hide the per-block __syncthreads phase.
//  - Inner loop: 1 LDS.32 weight (stride 55 words, odd -> conflict-free),
//    1 pack, 3 const-64b loads, 6 packed fma.rn.f32x2.

#define NJ   55
#define BT   128
#define BV   128   // vertices per block (1 per thread)

__constant__ ulonglong2 c_se3[NJ * 4];   // full [55][4][4] = 3520 B; rows 0..2 used

#define FMA2(acc, s, m) \
    asm("fma.rn.f32x2 %0, %1, %2, %0;" : "+l"(acc) : "l"(s), "l"(m))

#define PACK_DUP(dst, f) \
    asm("mov.b64 %0, {%1, %1};" : "=l"(dst) : "f"(f))

#define UNPACK2(lo, hi, src) \
    asm("mov.b64 {%0, %1}, %2;" : "=f"(lo), "=f"(hi) : "l"(src))

__global__ void __launch_bounds__(BT, 8) lbs_kernel(
    const float* __restrict__ points,   // [N,3]
    const float* __restrict__ weights,  // [N,55]
    float* __restrict__ out,            // [N,3]
    int N)
{
    __shared__ float w_s[BV * NJ];      // 28160 B

    const int tid   = threadIdx.x;
    const int vbase = blockIdx.x * BV;
    const int nv    = min(BV, N - vbase);

    // ---- stage weights tile: contiguous coalesced float4 copy ----
    {
        const long long base = (long long)vbase * NJ;
        const int nflt = nv * NJ;
        const int n4   = nflt >> 2;
        const float4* __restrict__ src = reinterpret_cast<const float4*>(weights + base);
        float4* dst = reinterpret_cast<float4*>(w_s);
        #pragma unroll 4
        for (int i = tid; i < n4; i += BT) dst[i] = src[i];
        for (int i = (n4 << 2) + tid; i < nflt; i += BT)
            w_s[i] = weights[base + i];
    }
    __syncthreads();

    const bool valid = (tid < nv);
    const int v  = vbase + tid;
    const int pv = valid ? v : 0;

    const float px = points[3 * pv + 0];
    const float py = points[3 * pv + 1];
    const float pz = points[3 * pv + 2];

    // A rows 0..2, each 4 floats = 2 f32x2 pairs
    unsigned long long a00 = 0, a01 = 0, a10 = 0, a11 = 0, a20 = 0, a21 = 0;

    const float* __restrict__ wp = w_s + tid * NJ;

    #pragma unroll 11
    for (int j = 0; j < NJ; j++) {
        const float w = wp[j];
        unsigned long long ww;
        PACK_DUP(ww, w);

        const ulonglong2 r0 = c_se3[j * 4 + 0];
        const ulonglong2 r1 = c_se3[j * 4 + 1];
        const ulonglong2 r2 = c_se3[j * 4 + 2];

        FMA2(a00, ww, r0.x); FMA2(a01, ww, r0.y);
        FMA2(a10, ww, r1.x); FMA2(a11, ww, r1.y);
        FMA2(a20, ww, r2.x); FMA2(a21, ww, r2.y);
    }

    // ---- epilogue: out = R*p + T ----
    if (valid) {
        float m0, m1, m2, m3, o0, o1, o2;
        UNPACK2(m0, m1, a00); UNPACK2(m2, m3, a01);
        o0 = fmaf(m0, px, fmaf(m1, py, fmaf(m2, pz, m3)));
        UNPACK2(m0, m1, a10); UNPACK2(m2, m3, a11);
        o1 = fmaf(m0, px, fmaf(m1, py, fmaf(m2, pz, m3)));
        UNPACK2(m0, m1, a20); UNPACK2(m2, m3, a21);
        o2 = fmaf(m0, px, fmaf(m1, py, fmaf(m2, pz, m3)));
        out[3 * v + 0] = o0;
        out[3 * v + 1] = o1;
        out[3 * v + 2] = o2;
    }
}

extern "C" void kernel_launch(void* const* d_in, const int* in_sizes, int n_in,
                              void* d_out, int out_size)
{
    const float* points  = (const float*)d_in[0];  // [N,3]
    const float* weights = (const float*)d_in[1];  // [N,55]
    const float* se3     = (const float*)d_in[2];  // [55,4,4]
    float* out           = (float*)d_out;          // [N,3]

    // Stage SE3 into constant memory (device-to-device, graph-capturable).
    cudaMemcpyToSymbolAsync(c_se3, se3, NJ * 4 * sizeof(ulonglong2), 0,
                            cudaMemcpyDeviceToDevice, 0);

    const int N = in_sizes[0] / 3;
    const int grid = (N + BV - 1) / BV;
    lbs_kernel<<<grid, BT>>>(points, weights, out, N);
}